// round 14
// baseline (speedup 1.0000x reference)
#include <cuda_runtime.h>
#include <cuda_pipeline_primitives.h>
#include <stdint.h>

#define NF      4096
#define THREADS 256
#define WSLICE  512               // floats per warp column-slice (NF/8)
#define STAGES  3                 // 3 x 16KB row buffers = 48KB static smem
#define GRID    592               // 4 blocks x 148 SMs, exact fill

// ---------------------------------------------------------------------------
// Build folded coefficient vector into sv (block-wide, 256 threads):
//   v[f] = sum_i [flat_idx[i]==f] * w_flat[i] * diag_w[seg_ids[i]] * dense_W[seg_ids[i]]
// Item loads batched 8-wide (3 rounds cover 6144 >= total=5115) -> high MLP,
// short dependent chain. Index dtype via low-word addressing: values < 2^31,
// little-endian -> fi32[i << is64] reads the value for int32 AND int64.
// Runs identically in every block: no global state, replay/profiler safe.
// ---------------------------------------------------------------------------
__device__ __noinline__ void build_v(float* sv,
                                     const void* fir,
                                     const void* sir,
                                     const float* w_flat,
                                     const float* diag_w,
                                     const float* dense_W,
                                     int total) {
    const int tid = threadIdx.x;

    const int* probe = (const int*)fir;
    int is64 = 1;
    #pragma unroll
    for (int k = 0; k < 16; k++) is64 &= (probe[2 * k + 1] == 0);

    for (int i = tid; i < NF; i += THREADS) sv[i] = 0.0f;
    __syncthreads();

    const int* fi32 = (const int*)fir;
    const int* sg32 = (const int*)sir;

    for (int c = 0; c < 3; c++) {
        int f[8], g[8]; float wf[8];
        #pragma unroll
        for (int k = 0; k < 8; k++) {
            int i = tid + (c * 8 + k) * THREADS;
            bool p = i < total;
            f[k]  = p ? fi32[i << is64] : 0;
            g[k]  = p ? sg32[i << is64] : 0;
            wf[k] = p ? w_flat[i]       : 0.0f;
        }
        float co[8];
        #pragma unroll
        for (int k = 0; k < 8; k++)
            co[k] = wf[k] * __ldg(&diag_w[g[k]]) * __ldg(&dense_W[g[k]]);
        #pragma unroll
        for (int k = 0; k < 8; k++)
            if (tid + (c * 8 + k) * THREADS < total) atomicAdd(&sv[f[k]], co[k]);
    }
    for (int i = tid + 24 * THREADS; i < total; i += THREADS) {  // robust tail
        int ff = fi32[i << is64], gg = sg32[i << is64];
        atomicAdd(&sv[ff], w_flat[i] * diag_w[gg] * dense_W[gg]);
    }
    __syncthreads();
}

// ---------------------------------------------------------------------------
// Single fused kernel, zero inter-block communication.
//  1. Prefetch rows 0,1 via cp.async (32KB/block) -> DRAM ramps immediately.
//  2. build_v into the spare stage sx[2] (overlapped with #1's latency and
//     the chip-wide first-wave ramp; index/weight arrays are L2-hot).
//  3. v-slice -> registers; reclaim sx[2] with row-2 prefetch.
//  4. R7-proven mainloop: 8 warps x 512-float column slices, 3-stage ring,
//     contiguous per-block row range, shuffle-reduce + REDG atomic per row.
// ---------------------------------------------------------------------------
__global__ void __launch_bounds__(THREADS, 4)
fused_kernel(const float* __restrict__ x,
             const void* flatidx,
             const void* segids,
             const float* w_flat,
             const float* diag_w,
             const float* dense_W,
             int total, int batch,
             float* out) {
    __shared__ __align__(16) float sx[STAGES][NF];   // 48KB; sx[2] stages v

    const int tid  = threadIdx.x;
    const int w    = tid >> 5;
    const int lane = tid & 31;
    const int bid  = blockIdx.x;
    const int grid = gridDim.x;

    // Contiguous row partition.
    const int base  = batch / grid;
    const int rem   = batch - base * grid;
    const int cnt   = base + (bid < rem);
    const int start = bid * base + (bid < rem ? bid : rem);

    const int woff = w * WSLICE;
    const float* xrow0 = x + (size_t)start * NF + woff;

    // ---- 1. Prefetch rows 0,1 immediately ----
    #pragma unroll
    for (int s = 0; s < 2; s++) {
        if (s < cnt) {
            const float* src = xrow0 + (size_t)s * NF;
            #pragma unroll
            for (int j = 0; j < 4; j++) {
                const int c = (lane + 32 * j) * 4;
                __pipeline_memcpy_async(&sx[s][woff + c], src + c, 16);
            }
        }
        __pipeline_commit();
    }

    // Zero this block's output rows (harness poisons d_out).
    for (int r = tid; r < cnt; r += THREADS) out[start + r] = 0.0f;

    // ---- 2. Build v into sx[2] (overlaps the in-flight prefetches) ----
    float* sv = sx[2];
    build_v(sv, flatidx, segids, w_flat, diag_w, dense_W, total);

    // ---- 3. v-slice into registers (build_v ends with __syncthreads) ----
    const float4* sv4 = (const float4*)(sv + woff);
    float4 v0 = sv4[lane +  0];
    float4 v1 = sv4[lane + 32];
    float4 v2 = sv4[lane + 64];
    float4 v3 = sv4[lane + 96];

    // Reclaim sx[2] with row-2 prefetch. Each thread overwrites exactly the
    // addresses it just read (same lane/chunk mapping) -> per-thread ordered,
    // cross-thread regions disjoint; producer reads completed at the sync.
    if (2 < cnt) {
        const float* src = xrow0 + (size_t)2 * NF;
        #pragma unroll
        for (int j = 0; j < 4; j++) {
            const int c = (lane + 32 * j) * 4;
            __pipeline_memcpy_async(&sx[2][woff + c], src + c, 16);
        }
    }
    __pipeline_commit();

    __syncthreads();   // out[] zeroing visible to all warps before atomics

    // ---- 4. Main loop: one row per iteration ----
    for (int i = 0; i < cnt; i++) {
        __pipeline_wait_prior(STAGES - 1);   // this thread's row-i chunks landed

        const int s = i % STAGES;
        const float4* xs = (const float4*)(sx[s] + woff);

        float4 xa = xs[lane +  0];
        float4 xb = xs[lane + 32];
        float4 xc = xs[lane + 64];
        float4 xd = xs[lane + 96];

        // Refill this slot with row i+STAGES (thread-local WAR safe).
        if (i + STAGES < cnt) {
            const float* src = xrow0 + (size_t)(i + STAGES) * NF;
            #pragma unroll
            for (int j = 0; j < 4; j++) {
                const int c = (lane + 32 * j) * 4;
                __pipeline_memcpy_async(&sx[s][woff + c], src + c, 16);
            }
        }
        __pipeline_commit();

        float a0 = xa.x * v0.x + xa.y * v0.y + xa.z * v0.z + xa.w * v0.w;
        float a1 = xb.x * v1.x + xb.y * v1.y + xb.z * v1.z + xb.w * v1.w;
        float a2 = xc.x * v2.x + xc.y * v2.y + xc.z * v2.z + xc.w * v2.w;
        float a3 = xd.x * v3.x + xd.y * v3.y + xd.z * v3.z + xd.w * v3.w;
        float acc = (a0 + a1) + (a2 + a3);

        #pragma unroll
        for (int o = 16; o; o >>= 1)
            acc += __shfl_xor_sync(0xffffffffu, acc, o);

        if (lane == 0) atomicAdd(&out[start + i], acc);  // REDG fire-and-forget
    }
}

// Inputs (metadata order): x [B*4096] f32, flat_idx [total], seg_ids [total],
// w_flat [total] f32, diag_w [1024] f32, dense_W [1024] f32. Output: [B] f32.
extern "C" void kernel_launch(void* const* d_in, const int* in_sizes, int n_in,
                              void* d_out, int out_size) {
    const float* x       = (const float*)d_in[0];
    const void*  flatidx = d_in[1];
    const void*  segids  = d_in[2];
    const float* w_flat  = (const float*)d_in[3];
    const float* diag_w  = (const float*)d_in[4];
    const float* dense_W = (const float*)d_in[5];

    int total = in_sizes[1];
    int batch = in_sizes[0] / NF;

    int blocks = batch < GRID ? batch : GRID;
    fused_kernel<<<blocks, THREADS>>>(x, flatidx, segids, w_flat, diag_w,
                                      dense_W, total, batch, (float*)d_out);
}

// round 15
// speedup vs baseline: 1.0661x; 1.0661x over previous
#include <cuda_runtime.h>
#include <cuda_pipeline_primitives.h>
#include <stdint.h>

#define NF        4096
#define THREADS   512
#define WARPS     16
#define WSLICE    (NF / WARPS)      // 256 floats per warp column-slice
#define STAGES    6                 // 6 x 16KB row buffers = 96KB dynamic smem
#define GRID      296               // 2 blocks x 148 SMs, exact fill

__device__ float g_v[NF];

// ---------------------------------------------------------------------------
// Kernel A: build folded coefficient vector (R8-validated).
//   v[f] = sum_i [flat_idx[i]==f] * w_flat[i] * diag_w[seg_ids[i]] * dense_W[seg_ids[i]]
// PDL trigger at entry; item loads batched (MLP~15); index dtype via low-word
// addressing (values < 2^31, LE -> fi32[i << is64] correct for int32/int64).
// ---------------------------------------------------------------------------
__global__ void __launch_bounds__(1024)
build_coef_kernel(const void* __restrict__ flat_idx_raw,
                  const void* __restrict__ seg_ids_raw,
                  const float* __restrict__ w_flat,
                  const float* __restrict__ diag_w,
                  const float* __restrict__ dense_W,
                  int total) {
    cudaTriggerProgrammaticLaunchCompletion();

    __shared__ float sv[NF];
    const int tid = threadIdx.x;

    const int* probe = (const int*)flat_idx_raw;
    int is64 = 1;
    #pragma unroll
    for (int k = 0; k < 16; k++) is64 &= (probe[2 * k + 1] == 0);

    for (int i = tid; i < NF; i += 1024) sv[i] = 0.0f;

    const int* fi32 = (const int*)flat_idx_raw;
    const int* sg32 = (const int*)seg_ids_raw;

    int   f[5], g[5];
    float wf[5];
    #pragma unroll
    for (int k = 0; k < 5; k++) {
        int i = tid + k * 1024;
        bool p = i < total;
        f[k]  = p ? fi32[i << is64] : 0;
        g[k]  = p ? sg32[i << is64] : 0;
        wf[k] = p ? w_flat[i]       : 0.0f;
    }
    float c[5];
    #pragma unroll
    for (int k = 0; k < 5; k++)
        c[k] = wf[k] * __ldg(&diag_w[g[k]]) * __ldg(&dense_W[g[k]]);

    __syncthreads();

    #pragma unroll
    for (int k = 0; k < 5; k++)
        if (tid + k * 1024 < total) atomicAdd(&sv[f[k]], c[k]);

    for (int i = tid + 5120; i < total; i += 1024) {   // robustness tail
        int ff = fi32[i << is64], gg = sg32[i << is64];
        atomicAdd(&sv[ff], w_flat[i] * diag_w[gg] * dense_W[gg]);
    }
    __syncthreads();

    for (int i = tid; i < NF; i += 1024) g_v[i] = sv[i];
}

// ---------------------------------------------------------------------------
// Kernel B: persistent GEMV combining the two best measured regimes:
//   - 32 warps/SM (2 blocks x 16 warps) -> R7's best DRAM% operating point
//   - 296-block grid + 96KB 6-stage ring prefetched pre-sync -> R8's proven
//     low-overhead PDL overlap
// Warp w owns columns [256w, 256w+256); v-slice = 2 float4 in registers.
// Block owns a contiguous row range (sequential DRAM stream).
// ---------------------------------------------------------------------------
__global__ void __launch_bounds__(THREADS, 2)
gemv_kernel(const float* __restrict__ x,
            float* __restrict__ out,
            int batch) {
    extern __shared__ __align__(16) float sx[];   // STAGES * NF floats

    const int tid  = threadIdx.x;
    const int w    = tid >> 5;
    const int lane = tid & 31;
    const int bid  = blockIdx.x;
    const int grid = gridDim.x;

    const int base  = batch / grid;
    const int rem   = batch - base * grid;
    const int cnt   = base + (bid < rem);
    const int start = bid * base + (bid < rem ? bid : rem);

    const int woff = w * WSLICE;
    const float* __restrict__ xrow0 = x + (size_t)start * NF + woff;

    // ---- Prefetch all STAGES rows pre-sync (96KB/block overlap window) ----
    #pragma unroll
    for (int s = 0; s < STAGES; s++) {
        if (s < cnt) {
            const float* src = xrow0 + (size_t)s * NF;
            float* dst = sx + s * NF + woff;
            #pragma unroll
            for (int j = 0; j < 2; j++) {
                const int c = (lane + 32 * j) * 4;
                __pipeline_memcpy_async(dst + c, src + c, 16);
            }
        }
        __pipeline_commit();
    }

    // Zero this block's output rows (harness poisons d_out); pre-sync.
    for (int r = tid; r < cnt; r += THREADS) out[start + r] = 0.0f;

    // Wait for build_coef_kernel (g_v ready).
    cudaGridDependencySynchronize();

    // This lane's v-slice: 2 float4 in registers.
    const float4* __restrict__ gv4 = (const float4*)(g_v + woff);
    float4 v0 = __ldg(&gv4[lane +  0]);
    float4 v1 = __ldg(&gv4[lane + 32]);

    __syncthreads();   // out[] zeroing visible before atomics

    // ---- Main loop: one row per iteration, 6-deep ring ----
    for (int i = 0; i < cnt; i++) {
        __pipeline_wait_prior(STAGES - 1);   // this thread's row-i chunks landed

        const int s = i % STAGES;
        const float4* __restrict__ xs = (const float4*)(sx + s * NF + woff);

        float4 xa = xs[lane +  0];
        float4 xb = xs[lane + 32];

        // Refill this slot with row i+STAGES (thread-local WAR safe).
        if (i + STAGES < cnt) {
            const float* src = xrow0 + (size_t)(i + STAGES) * NF;
            float* dst = sx + s * NF + woff;
            #pragma unroll
            for (int j = 0; j < 2; j++) {
                const int c = (lane + 32 * j) * 4;
                __pipeline_memcpy_async(dst + c, src + c, 16);
            }
        }
        __pipeline_commit();

        float a0 = xa.x * v0.x + xa.y * v0.y + xa.z * v0.z + xa.w * v0.w;
        float a1 = xb.x * v1.x + xb.y * v1.y + xb.z * v1.z + xb.w * v1.w;
        float acc = a0 + a1;

        #pragma unroll
        for (int o = 16; o; o >>= 1)
            acc += __shfl_xor_sync(0xffffffffu, acc, o);

        if (lane == 0) atomicAdd(&out[start + i], acc);  // REDG fire-and-forget
    }
}

// Inputs (metadata order): x [B*4096] f32, flat_idx [total], seg_ids [total],
// w_flat [total] f32, diag_w [1024] f32, dense_W [1024] f32. Output: [B] f32.
extern "C" void kernel_launch(void* const* d_in, const int* in_sizes, int n_in,
                              void* d_out, int out_size) {
    const float* x       = (const float*)d_in[0];
    const void*  flatidx = d_in[1];
    const void*  segids  = d_in[2];
    const float* w_flat  = (const float*)d_in[3];
    const float* diag_w  = (const float*)d_in[4];
    const float* dense_W = (const float*)d_in[5];

    int total = in_sizes[1];
    int batch = in_sizes[0] / NF;

    const int smem_bytes = STAGES * NF * sizeof(float);   // 96 KB
    static bool attr_set = false;
    if (!attr_set) {
        cudaFuncSetAttribute(gemv_kernel,
                             cudaFuncAttributeMaxDynamicSharedMemorySize,
                             smem_bytes);
        attr_set = true;
    }

    build_coef_kernel<<<1, 1024>>>(flatidx, segids, w_flat, diag_w, dense_W,
                                   total);

    int blocks = batch < GRID ? batch : GRID;
    float* outp = (float*)d_out;

    cudaLaunchConfig_t cfg = {};
    cfg.gridDim  = dim3(blocks, 1, 1);
    cfg.blockDim = dim3(THREADS, 1, 1);
    cfg.dynamicSmemBytes = smem_bytes;
    cfg.stream = 0;

    cudaLaunchAttribute attr;
    attr.id = cudaLaunchAttributeProgrammaticStreamSerialization;
    attr.val.programmaticStreamSerializationAllowed = 1;
    cfg.attrs = &attr;
    cfg.numAttrs = 1;

    cudaLaunchKernelEx(&cfg, gemv_kernel, x, outp, batch);
}